// round 8
// baseline (speedup 1.0000x reference)
#include <cuda_runtime.h>
#include <cuda_bf16.h>

// SENet gating: persistent blocks + double-buffered block-granular TMA.
// Each 128-thread block loops over 16-row tiles (12032 B) strided by grid:
//   prologue: bulk-load tiles t0 (buf0) and t0+G (buf1)
//   iter:  parity-wait buf b  ->  seg-sums (64 thr)  ->  MLP (16 thr)
//          ->  gate-mul in place (128 thr)  ->  commit bulk store
//          ->  wait store read-drain  ->  bulk-load tile t+2G into buf b
// Every tile's load is in flight a full iteration (~7000 cy) before use;
// DRAM latency is never exposed. Footprint (26 KB smem, <=64 regs) keeps
// 8 blocks/SM -- the occupancy that produced 81% DRAM in R7.

#define NFEAT 188
#define NF4   47
#define ROWS_TILE 16
#define TILE_F (ROWS_TILE * NFEAT)   // 3008 floats = 12032 B
#define NTHREADS 128
#define MAX_BLOCKS (152 * 8)         // 1216

// packed segment ids for the 4 features of each float4 position (0..46)
__device__ __constant__ unsigned int c_stab[47] = {
    0x00000000u,0x00000000u,0x00000000u,0x00000000u,0x00000000u,
    0x01010101u,0x02020101u,0x02020202u,0x02020202u,0x02020202u,
    0x02020202u,0x03020202u,0x03030303u,0x03030303u,0x03030303u,
    0x03030303u,0x04030303u,0x04040404u,0x05050504u,0x05050505u,
    0x05050505u,0x05050505u,0x05050505u,0x06060505u,0x06060606u,
    0x06060606u,0x06060606u,0x06060606u,0x07070606u,0x07070707u,
    0x08080808u,0x08080808u,0x08080808u,0x08080808u,0x08080808u,
    0x09090908u,0x09090909u,0x09090909u,0x09090909u,0x09090909u,
    0x0A0A0A09u,0x0B0A0A0Au,0x0B0B0B0Bu,0x0B0B0B0Bu,0x0B0B0B0Bu,
    0x0B0B0B0Bu,0x0B0B0B0Bu
};

__device__ __forceinline__ void mbar_wait(unsigned int mb, int parity) {
    unsigned int done;
    asm volatile(
        "{\n\t.reg .pred p;\n\t"
        "mbarrier.try_wait.parity.acquire.cta.shared::cta.b64 p, [%1], %2;\n\t"
        "selp.b32 %0, 1, 0, p;\n\t}"
        : "=r"(done) : "r"(mb), "r"((unsigned)parity) : "memory");
    if (!done) {
        asm volatile(
            "{\n\t.reg .pred p;\n"
            "W_%=:\n\t"
            "mbarrier.try_wait.parity.acquire.cta.shared::cta.b64 p, [%0], %1, 0x989680;\n\t"
            "@p bra D_%=;\n\t"
            "bra.uni W_%=;\n"
            "D_%=:\n\t}"
            :: "r"(mb), "r"((unsigned)parity) : "memory");
    }
}

__global__ __launch_bounds__(NTHREADS, 8)
void senet_kernel(const float* __restrict__ x,
                  const float* __restrict__ W1,   // [3,12]
                  const float* __restrict__ b1,   // [3]
                  const float* __restrict__ W2,   // [12,3]
                  const float* __restrict__ b2,   // [12]
                  float* __restrict__ out,
                  int B, int T, int G)            // T tiles, G grid stride
{
    __shared__ __align__(16) float sx[2][TILE_F];           // 24064 B
    __shared__ __align__(8)  unsigned long long smbar[2];
    __shared__ float        smeans[ROWS_TILE][12];
    __shared__ float        sgates[ROWS_TILE][13];
    __shared__ float        sw[88];
    __shared__ unsigned int sstab[47];

    const int tid = threadIdx.x;

    // ---- one-time init ----
    if (tid == 0) {
        unsigned int m0 = (unsigned int)__cvta_generic_to_shared(&smbar[0]);
        unsigned int m1 = (unsigned int)__cvta_generic_to_shared(&smbar[1]);
        asm volatile("mbarrier.init.shared.b64 [%0], 1;" :: "r"(m0) : "memory");
        asm volatile("mbarrier.init.shared.b64 [%0], 1;" :: "r"(m1) : "memory");
        asm volatile("fence.proxy.async.shared::cta;" ::: "memory");
    }
    if (tid < 47) sstab[tid] = c_stab[tid];
    for (int j = tid; j < 87; j += NTHREADS) {
        float v;
        if      (j < 36) v = __ldg(W1 + j);
        else if (j < 39) v = __ldg(b1 + (j - 36));
        else if (j < 75) v = __ldg(W2 + (j - 39));
        else             v = __ldg(b2 + (j - 75));
        sw[j] = v;
    }
    __syncthreads();

    const unsigned int mbv[2] = {
        (unsigned int)__cvta_generic_to_shared(&smbar[0]),
        (unsigned int)__cvta_generic_to_shared(&smbar[1]) };
    const unsigned int sdv[2] = {
        (unsigned int)__cvta_generic_to_shared(&sx[0][0]),
        (unsigned int)__cvta_generic_to_shared(&sx[1][0]) };

    const int t0 = blockIdx.x;
    if (t0 >= T) return;

    // ---- issue one bulk load: tile -> buffer b ----
    auto issue = [&](int tile, int b) {
        int rows = B - tile * ROWS_TILE;
        if (rows > ROWS_TILE) rows = ROWS_TILE;
        const unsigned int bytes = (unsigned int)(rows * NFEAT) * 4u;
        const char* g = (const char*)(x + (long long)tile * TILE_F);
        asm volatile("mbarrier.arrive.expect_tx.shared.b64 _, [%0], %1;"
                     :: "r"(mbv[b]), "r"(bytes) : "memory");
        asm volatile(
            "cp.async.bulk.shared::cluster.global.mbarrier::complete_tx::bytes"
            " [%0], [%1], %2, [%3];"
            :: "r"(sdv[b]), "l"(g), "r"(bytes), "r"(mbv[b]) : "memory");
    };

    if (tid == 0) {
        issue(t0, 0);
        if (t0 + G < T) issue(t0 + G, 1);
    }

    int ph0 = 0, ph1 = 0;
    for (int it = 0; ; ++it) {
        const int tile = t0 + it * G;
        if (tile >= T) break;
        const int b = it & 1;

        // wait for the tile (acquire)
        mbar_wait(mbv[b], b ? ph1 : ph0);
        if (b) ph1 ^= 1; else ph0 ^= 1;

        int rows = B - tile * ROWS_TILE;
        if (rows > ROWS_TILE) rows = ROWS_TILE;
        float* sb = &sx[b][0];

        // ---- segment sums: 64 threads, (row = tid/4, quarter = tid&3) ----
        if (tid < 64) {
            const int row = tid >> 2;
            const int q   = tid & 3;
            if (row < rows) {
                const float* xr = sb + row * NFEAT + q * 47;
                float a0 = 0.f, a1 = 0.f, a2 = 0.f;
                #pragma unroll
                for (int j = 0;  j < 20; ++j) a0 += xr[j];
                #pragma unroll
                for (int j = 20; j < 26; ++j) a1 += xr[j];
                #pragma unroll
                for (int j = 26; j < 47; ++j) a2 += xr[j];
                smeans[row][3 * q + 0] = a0 * (1.f / 20.f);
                smeans[row][3 * q + 1] = a1 * (1.f / 6.f);
                smeans[row][3 * q + 2] = a2 * (1.f / 21.f);
            }
        }
        __syncthreads();

        // ---- tiny MLP 12->3(relu)->12(sigmoid), one thread per row ----
        if (tid < rows) {
            float m[12];
            #pragma unroll
            for (int k = 0; k < 12; ++k) m[k] = smeans[tid][k];
            float h[3];
            #pragma unroll
            for (int j = 0; j < 3; ++j) {
                float a = sw[36 + j];
                #pragma unroll
                for (int k = 0; k < 12; ++k) a += m[k] * sw[j * 12 + k];
                h[j] = fmaxf(a, 0.f);
            }
            #pragma unroll
            for (int s = 0; s < 12; ++s) {
                float a = sw[75 + s];
                #pragma unroll
                for (int j = 0; j < 3; ++j) a += h[j] * sw[39 + s * 3 + j];
                sgates[tid][s] = __fdividef(1.f, 1.f + __expf(-a));
            }
        }
        __syncthreads();

        // ---- gate multiply IN PLACE, all 128 threads ----
        {
            float4* sb4 = (float4*)sb;
            const int n4 = rows * NF4;
            #pragma unroll 3
            for (int i = tid; i < n4; i += NTHREADS) {
                const int row = i / NF4;
                const int p   = i - row * NF4;
                const unsigned int sid = sstab[p];
                const float* gr = sgates[row];
                float4 v = sb4[i];
                v.x *= gr[sid         & 255];
                v.y *= gr[(sid >> 8)  & 255];
                v.z *= gr[(sid >> 16) & 255];
                v.w *= gr[ sid >> 24       ];
                sb4[i] = v;
            }
        }
        __syncthreads();

        // ---- store tile; refill this buffer for tile + 2G ----
        if (tid == 0) {
            const unsigned int bytes = (unsigned int)(rows * NFEAT) * 4u;
            char* gdst = (char*)(out + (long long)tile * TILE_F);
            asm volatile("fence.proxy.async.shared::cta;" ::: "memory");
            asm volatile(
                "cp.async.bulk.global.shared::cta.bulk_group [%0], [%1], %2;"
                :: "l"(gdst), "r"(sdv[b]), "r"(bytes) : "memory");
            asm volatile("cp.async.bulk.commit_group;" ::: "memory");
            const int nxt = tile + 2 * G;
            if (nxt < T) {
                // buffer b reused by the next load: its store must finish
                // reading smem first (other 127 threads keep computing)
                asm volatile("cp.async.bulk.wait_group.read 0;" ::: "memory");
                issue(nxt, b);
            }
        }
    }

    // drain remaining stores before the block retires
    if (tid == 0) {
        asm volatile("cp.async.bulk.wait_group.read 0;" ::: "memory");
    }
}

extern "C" void kernel_launch(void* const* d_in, const int* in_sizes, int n_in,
                              void* d_out, int out_size)
{
    const float* x  = (const float*)d_in[0];
    const float* W1 = (const float*)d_in[1];
    const float* b1 = (const float*)d_in[2];
    const float* W2 = (const float*)d_in[3];
    const float* b2 = (const float*)d_in[4];
    float* out = (float*)d_out;

    const int B = in_sizes[0] / NFEAT;
    const int T = (B + ROWS_TILE - 1) / ROWS_TILE;
    int grid = MAX_BLOCKS;
    if (grid > T) grid = T;
    senet_kernel<<<grid, NTHREADS>>>(x, W1, b1, W2, b2, out, B, T, grid);
}

// round 9
// speedup vs baseline: 1.1789x; 1.1789x over previous
#include <cuda_runtime.h>
#include <cuda_bf16.h>

// SENet gating, block-granular TMA (R7 shape) + L2 evict_first hints.
// Each 128-thread block handles 32 rows (24064 B):
//   1. thread 0 issues ONE cp.async.bulk (24 KB) gmem->smem with
//      L2::evict_first (streaming read, zero reuse); all threads parity-wait
//   2. per-warp segment sums: lane (row=lane/4, quarter=lane&3) over its
//      contiguous 47-float slice (pattern (20,6,21) x 4)
//   3. MLP 12->3->12 (relu, sigmoid), one lane per row, weights from smem
//   4. gate-mul IN PLACE, __syncthreads, ONE 24 KB bulk store with
//      L2::evict_first (never re-read), drain before exit

#define NFEAT 188
#define NF4   47
#define R     8                    // rows per warp
#define WARPS 4
#define NTHREADS (WARPS * 32)
#define ROWS_BLK (WARPS * R)       // 32
#define TILE_F  (ROWS_BLK * NFEAT) // 6016 floats = 24064 B

// packed segment ids for the 4 features of each float4 position (0..46)
__device__ __constant__ unsigned int c_stab[47] = {
    0x00000000u,0x00000000u,0x00000000u,0x00000000u,0x00000000u,
    0x01010101u,0x02020101u,0x02020202u,0x02020202u,0x02020202u,
    0x02020202u,0x03020202u,0x03030303u,0x03030303u,0x03030303u,
    0x03030303u,0x04030303u,0x04040404u,0x05050504u,0x05050505u,
    0x05050505u,0x05050505u,0x05050505u,0x06060505u,0x06060606u,
    0x06060606u,0x06060606u,0x06060606u,0x07070606u,0x07070707u,
    0x08080808u,0x08080808u,0x08080808u,0x08080808u,0x08080808u,
    0x09090908u,0x09090909u,0x09090909u,0x09090909u,0x09090909u,
    0x0A0A0A09u,0x0B0A0A0Au,0x0B0B0B0Bu,0x0B0B0B0Bu,0x0B0B0B0Bu,
    0x0B0B0B0Bu,0x0B0B0B0Bu
};

__global__ __launch_bounds__(NTHREADS, 8)
void senet_kernel(const float* __restrict__ x,
                  const float* __restrict__ W1,   // [3,12]
                  const float* __restrict__ b1,   // [3]
                  const float* __restrict__ W2,   // [12,3]
                  const float* __restrict__ b2,   // [12]
                  float* __restrict__ out,
                  int B)
{
    __shared__ __align__(16) float sx[TILE_F];              // 24064 B
    __shared__ __align__(8)  unsigned long long smbar;
    __shared__ float        smeans[WARPS][R][12];
    __shared__ float        sgates[WARPS][R][13];
    __shared__ float        sw[88];
    __shared__ unsigned int sstab[47];

    const int tid  = threadIdx.x;
    const int lane = tid & 31;
    const int w    = tid >> 5;

    const long long brow0 = (long long)blockIdx.x * ROWS_BLK;
    int rows_blk = B - (int)brow0;
    if (rows_blk > ROWS_BLK) rows_blk = ROWS_BLK;
    const unsigned int bytes = (unsigned int)(rows_blk * NFEAT) * 4u;

    const unsigned int sdst = (unsigned int)__cvta_generic_to_shared(sx);
    const unsigned int mb   = (unsigned int)__cvta_generic_to_shared(&smbar);
    const char* gsrc = (const char*)(x   + brow0 * NFEAT);
    char*       gdst = (char*)      (out + brow0 * NFEAT);

    // ---- phase 0: init barrier, stage tables; ONE bulk load (evict_first) ----
    if (tid == 0) {
        asm volatile("mbarrier.init.shared.b64 [%0], 1;" :: "r"(mb) : "memory");
        asm volatile("fence.proxy.async.shared::cta;" ::: "memory");
        asm volatile("mbarrier.arrive.expect_tx.shared.b64 _, [%0], %1;"
                     :: "r"(mb), "r"(bytes) : "memory");
        asm volatile(
            "{\n\t.reg .b64 pol;\n\t"
            "createpolicy.fractional.L2::evict_first.b64 pol, 1.0;\n\t"
            "cp.async.bulk.shared::cluster.global.mbarrier::complete_tx::bytes.L2::cache_hint"
            " [%0], [%1], %2, [%3], pol;\n\t}"
            :: "r"(sdst), "l"(gsrc), "r"(bytes), "r"(mb) : "memory");
    }
    if (tid < 47) sstab[tid] = c_stab[tid];
    for (int j = tid; j < 87; j += NTHREADS) {
        float v;
        if      (j < 36) v = __ldg(W1 + j);
        else if (j < 39) v = __ldg(b1 + (j - 36));
        else if (j < 75) v = __ldg(W2 + (j - 39));
        else             v = __ldg(b2 + (j - 75));
        sw[j] = v;
    }
    __syncthreads();    // mbarrier.init + tables visible to all warps

    // ---- wait for tile (parity 0), every thread ----
    {
        unsigned int done;
        asm volatile(
            "{\n\t.reg .pred p;\n\t"
            "mbarrier.try_wait.parity.acquire.cta.shared::cta.b64 p, [%1], 0;\n\t"
            "selp.b32 %0, 1, 0, p;\n\t}"
            : "=r"(done) : "r"(mb) : "memory");
        if (!done) {
            asm volatile(
                "{\n\t.reg .pred p;\n"
                "W_%=:\n\t"
                "mbarrier.try_wait.parity.acquire.cta.shared::cta.b64 p, [%0], 0, 0x989680;\n\t"
                "@p bra D_%=;\n\t"
                "bra.uni W_%=;\n"
                "D_%=:\n\t}"
                :: "r"(mb) : "memory");
        }
    }
    __syncwarp();

    // per-warp row count
    int rows = rows_blk - w * R;
    if (rows < 0) rows = 0;
    if (rows > R) rows = R;
    float* sxw = sx + w * (R * NFEAT);

    // ---- phase 2: segment sums (balanced, bank-conflict-free) ----
    {
        const int rq = lane >> 2;
        const int sq = lane & 3;
        if (rq < rows) {
            const float* xr = sxw + rq * NFEAT + sq * 47;
            float a0 = 0.f, a1 = 0.f, a2 = 0.f;
            #pragma unroll
            for (int j = 0;  j < 20; ++j) a0 += xr[j];
            #pragma unroll
            for (int j = 20; j < 26; ++j) a1 += xr[j];
            #pragma unroll
            for (int j = 26; j < 47; ++j) a2 += xr[j];
            smeans[w][rq][3 * sq + 0] = a0 * (1.f / 20.f);
            smeans[w][rq][3 * sq + 1] = a1 * (1.f / 6.f);
            smeans[w][rq][3 * sq + 2] = a2 * (1.f / 21.f);
        }
    }
    __syncwarp();

    // ---- phase 3: tiny MLP, one lane per row ----
    if (lane < rows) {
        float m[12];
        #pragma unroll
        for (int k = 0; k < 12; ++k) m[k] = smeans[w][lane][k];
        float h[3];
        #pragma unroll
        for (int j = 0; j < 3; ++j) {
            float a = sw[36 + j];
            #pragma unroll
            for (int k = 0; k < 12; ++k) a += m[k] * sw[j * 12 + k];
            h[j] = fmaxf(a, 0.f);
        }
        #pragma unroll
        for (int s = 0; s < 12; ++s) {
            float a = sw[75 + s];
            #pragma unroll
            for (int j = 0; j < 3; ++j) a += h[j] * sw[39 + s * 3 + j];
            sgates[w][lane][s] = __fdividef(1.f, 1.f + __expf(-a));
        }
    }
    __syncwarp();

    // ---- phase 4: gate multiply IN PLACE (warp's own subregion) ----
    {
        float4* sxw4 = (float4*)sxw;
        const int n4 = rows * NF4;
        #pragma unroll 3
        for (int i = lane; i < n4; i += 32) {
            const int row = i / NF4;
            const int p   = i - row * NF4;
            const unsigned int sid = sstab[p];
            const float* gr = sgates[w][row];
            float4 v = sxw4[i];
            v.x *= gr[sid         & 255];
            v.y *= gr[(sid >> 8)  & 255];
            v.z *= gr[(sid >> 16) & 255];
            v.w *= gr[ sid >> 24       ];
            sxw4[i] = v;
        }
    }
    __syncthreads();    // all warps' STS done before the bulk store

    // ---- phase 5: ONE 24 KB bulk store (evict_first); drain before exit ----
    if (tid == 0) {
        asm volatile("fence.proxy.async.shared::cta;" ::: "memory");
        asm volatile(
            "{\n\t.reg .b64 pol;\n\t"
            "createpolicy.fractional.L2::evict_first.b64 pol, 1.0;\n\t"
            "cp.async.bulk.global.shared::cta.bulk_group.L2::cache_hint"
            " [%0], [%1], %2, pol;\n\t}"
            :: "l"(gdst), "r"(sdst), "r"(bytes) : "memory");
        asm volatile("cp.async.bulk.commit_group;" ::: "memory");
        asm volatile("cp.async.bulk.wait_group.read 0;" ::: "memory");
    }
}

extern "C" void kernel_launch(void* const* d_in, const int* in_sizes, int n_in,
                              void* d_out, int out_size)
{
    const float* x  = (const float*)d_in[0];
    const float* W1 = (const float*)d_in[1];
    const float* b1 = (const float*)d_in[2];
    const float* W2 = (const float*)d_in[3];
    const float* b2 = (const float*)d_in[4];
    float* out = (float*)d_out;

    const int B = in_sizes[0] / NFEAT;
    const int grid = (B + ROWS_BLK - 1) / ROWS_BLK;
    senet_kernel<<<grid, NTHREADS>>>(x, W1, b1, W2, b2, out, B);
}